// round 7
// baseline (speedup 1.0000x reference)
#include <cuda_runtime.h>
#include <cuda_bf16.h>
#include <math.h>
#include <stdint.h>

// Problem constants (SelectiveSSM): B=4, L=4096, d_inner=2048, N=16
#define BATCH 4
#define LSEQ  4096
#define DIM   2048
#define NST   16
#define M_TOT (BATCH * LSEQ)   // 16384
#define DT_MIN_F 1e-4f

#define TK      64             // K elems (bf16) per chunk
#define NCHUNK  (DIM / TK)     // 32

// Padded smem row: 64 data + 8 pad bf16 -> 144B row stride (4-bank shift/row).
#define ROW_E   72
#define TILE_E  (128 * ROW_E)          // elements
#define TILE_B  (TILE_E * 2)           // bytes  (18432)
#define BUF_B   (4 * TILE_B)           // Ah, Al, Bh, Bl  (73728)
#define GEMM_SMEM_BYTES (2 * BUF_B)    // double buffer   (147456)

// ---------------- device scratch (static: no dynamic allocation allowed) ----
__device__ float          g_proj[3][(size_t)M_TOT * DIM];       // dt/b/c fp32
__device__ unsigned short g_uhi[(size_t)M_TOT * DIM];           // bf16 hi(U)
__device__ unsigned short g_ulo[(size_t)M_TOT * DIM];           // bf16 lo(U)
__device__ unsigned short g_wthi[3][(size_t)DIM * DIM];         // bf16 hi(W^T)
__device__ unsigned short g_wtlo[3][(size_t)DIM * DIM];         // bf16 lo(W^T)

// ---------------- small helpers --------------------------------------------
__device__ __forceinline__ float softplus_acc(float x) {
    return log1pf(expf(-fabsf(x))) + fmaxf(x, 0.0f);
}
__device__ __forceinline__ unsigned short f2bf(float x) {
    __nv_bfloat16 h = __float2bfloat16(x);
    return *reinterpret_cast<unsigned short*>(&h);
}
__device__ __forceinline__ float bf2f(unsigned short s) {
    __nv_bfloat16 h;
    *reinterpret_cast<unsigned short*>(&h) = s;
    return __bfloat162float(h);
}
__device__ __forceinline__ uint32_t smem_u32(const void* p) {
    uint32_t a;
    asm("{ .reg .u64 t; cvta.to.shared.u64 t, %1; cvt.u32.u64 %0, t; }"
        : "=r"(a) : "l"(p));
    return a;
}
__device__ __forceinline__ void ldsm_x4(uint32_t (&r)[4], uint32_t addr) {
    asm volatile("ldmatrix.sync.aligned.m8n8.x4.shared.b16 {%0,%1,%2,%3}, [%4];"
                 : "=r"(r[0]), "=r"(r[1]), "=r"(r[2]), "=r"(r[3]) : "r"(addr));
}
// D += A(16x16 bf16, row) @ B(16x8 bf16, col), fp32 accum
__device__ __forceinline__ void mma16816(float* c, const uint32_t* a,
                                         const uint32_t* b) {
    asm volatile(
        "mma.sync.aligned.m16n8k16.row.col.f32.bf16.bf16.f32 "
        "{%0,%1,%2,%3}, {%4,%5,%6,%7}, {%8,%9}, {%0,%1,%2,%3};"
        : "+f"(c[0]), "+f"(c[1]), "+f"(c[2]), "+f"(c[3])
        : "r"(a[0]), "r"(a[1]), "r"(a[2]), "r"(a[3]), "r"(b[0]), "r"(b[1]));
}

// ---------------------------------------------------------------------------
// Conversion: U fp32 -> (hi, lo) bf16
// ---------------------------------------------------------------------------
__global__ __launch_bounds__(256)
void conv_u_k(const float* __restrict__ u) {
    size_t i = ((size_t)blockIdx.x * 256 + threadIdx.x) * 4;
    float4 v = *(const float4*)(u + i);
    ushort4 hi, lo;
    hi.x = f2bf(v.x); lo.x = f2bf(v.x - bf2f(hi.x));
    hi.y = f2bf(v.y); lo.y = f2bf(v.y - bf2f(hi.y));
    hi.z = f2bf(v.z); lo.z = f2bf(v.z - bf2f(hi.z));
    hi.w = f2bf(v.w); lo.w = f2bf(v.w - bf2f(hi.w));
    *(ushort4*)(g_uhi + i) = hi;
    *(ushort4*)(g_ulo + i) = lo;
}

// ---------------------------------------------------------------------------
// Conversion + transpose: W[k][n] fp32 -> Wt hi/lo bf16 [n][k]
// ---------------------------------------------------------------------------
__global__ __launch_bounds__(256)
void conv_w_k(const float* __restrict__ Wdt, const float* __restrict__ Wb,
              const float* __restrict__ Wc) {
    const int z = blockIdx.z;
    const float* W = (z == 0) ? Wdt : (z == 1) ? Wb : Wc;
    __shared__ float tile[32][33];
    const int tx = threadIdx.x, ty = threadIdx.y;  // 32 x 8
    const int k0 = blockIdx.y * 32, n0 = blockIdx.x * 32;
#pragma unroll
    for (int i = 0; i < 4; i++)
        tile[ty + 8 * i][tx] = W[(size_t)(k0 + ty + 8 * i) * DIM + n0 + tx];
    __syncthreads();
#pragma unroll
    for (int i = 0; i < 4; i++) {
        const int n = n0 + ty + 8 * i;
        float x = tile[tx][ty + 8 * i];
        unsigned short h = f2bf(x);
        g_wthi[z][(size_t)n * DIM + k0 + tx] = h;
        g_wtlo[z][(size_t)n * DIM + k0 + tx] = f2bf(x - bf2f(h));
    }
}

// ---------------------------------------------------------------------------
// Projection GEMM via mma.sync (HMMA): g_proj[z][m][n] = sum_k U W_z + bias.
// Split-bf16, 3 terms (hi*hi + hi*lo + lo*hi), fp32 accumulators
// (dropped lo*lo term contributes ~2^-16 relative — far below 1e-3 budget;
//  keeping all three cross terms holds total error ~1e-5).
// CTA 128x128 tile, 8 warps (2x4), warp tile 64x32 via m16n8k16.
// Double-buffered cp.async smem pipeline over K chunks of 64.
// ---------------------------------------------------------------------------
__global__ __launch_bounds__(256)
void proj_gemm_mma(const float* __restrict__ bdt, const float* __restrict__ bb,
                   const float* __restrict__ bc) {
    extern __shared__ __align__(16) unsigned short smem[];
    const uint32_t ubase = smem_u32(smem);

    const int tid  = threadIdx.x;
    const int wid  = tid >> 5, lane = tid & 31;
    const int wm   = wid >> 2;           // warp m 0..1  (64 rows)
    const int wn   = wid & 3;            // warp n 0..3  (32 cols)
    const int z    = blockIdx.z;
    const int m0   = blockIdx.y * 128;
    const int n0   = blockIdx.x * 128;

    const unsigned short* Ah = g_uhi;
    const unsigned short* Al = g_ulo;
    const unsigned short* Bh = g_wthi[z];
    const unsigned short* Bl = g_wtlo[z];
    const float* bias = (z == 0) ? bdt : (z == 1) ? bb : bc;

    float acc[4][4][4];
#pragma unroll
    for (int mi = 0; mi < 4; mi++)
#pragma unroll
        for (int ni = 0; ni < 4; ni++)
#pragma unroll
            for (int q = 0; q < 4; q++) acc[mi][ni][q] = 0.0f;

    // Staging: 1024 16B-chunks per tile / 256 thr = 4 per thread per tile.
    const int srow = tid >> 3;     // 0..31 (+32 per i)
    const int sc16 = tid & 7;      // 16B unit within the 128B data of a row
    auto load_chunk = [&](int c) {
        const uint32_t bufb = ubase + (uint32_t)(c & 1) * BUF_B;
        const int k0 = c * TK;
        const unsigned short* srcs[4] = { Ah, Al, Bh, Bl };
#pragma unroll
        for (int t = 0; t < 4; t++) {
            const int row0 = (t < 2) ? m0 : n0;
            const unsigned short* sp = srcs[t];
            const uint32_t tb = bufb + (uint32_t)t * TILE_B;
#pragma unroll
            for (int i = 0; i < 4; i++) {
                const int row = srow + i * 32;
                const unsigned short* gp =
                    sp + (size_t)(row0 + row) * DIM + k0 + sc16 * 8;
                const uint32_t so = tb + (uint32_t)(row * ROW_E + sc16 * 8) * 2;
                asm volatile("cp.async.cg.shared.global [%0], [%1], 16;"
                             :: "r"(so), "l"(gp));
            }
        }
        asm volatile("cp.async.commit_group;" ::: "memory");
    };

    load_chunk(0);   // prime

    for (int c = 0; c < NCHUNK; c++) {
        const uint32_t bufb = ubase + (uint32_t)(c & 1) * BUF_B;
        if (c + 1 < NCHUNK) {
            load_chunk(c + 1);                               // into buf (c+1)&1
            asm volatile("cp.async.wait_group 1;" ::: "memory");  // c resident
        } else {
            asm volatile("cp.async.wait_group 0;" ::: "memory");
        }
        __syncthreads();   // chunk c visible to all warps

        const uint32_t Ahb = bufb;
        const uint32_t Alb = bufb + TILE_B;
        const uint32_t Bhb = bufb + 2 * TILE_B;
        const uint32_t Blb = bufb + 3 * TILE_B;

        // A-frag addr: row wm*64+mi*16+(lane&15), col ks*16+(lane>>4)*8
        const int ar = wm * 64 + (lane & 15);
        const int ak = (lane >> 4) * 8;
        // B-frag addr (x4 covers two 8-col n-tiles x two k-halves)
        const int bsub = lane >> 3;            // 0..3
        const int brw  = lane & 7;
        const int bkg  = (bsub & 1) * 8;       // k-half
        const int bnt  = bsub >> 1;            // n-tile within pair

#pragma unroll
        for (int ks = 0; ks < 4; ks++) {
            uint32_t ah[4][4], al[4][4], bh[4][2], bl[4][2];
#pragma unroll
            for (int mi = 0; mi < 4; mi++) {
                const uint32_t off =
                    (uint32_t)((ar + mi * 16) * ROW_E + ks * 16 + ak) * 2;
                ldsm_x4(ah[mi], Ahb + off);
                ldsm_x4(al[mi], Alb + off);
            }
#pragma unroll
            for (int nj = 0; nj < 2; nj++) {
                const int brow = wn * 32 + (nj * 2 + bnt) * 8 + brw;
                const uint32_t off =
                    (uint32_t)(brow * ROW_E + ks * 16 + bkg) * 2;
                uint32_t th[4], tl[4];
                ldsm_x4(th, Bhb + off);
                ldsm_x4(tl, Blb + off);
                bh[nj * 2][0] = th[0]; bh[nj * 2][1] = th[1];
                bh[nj * 2 + 1][0] = th[2]; bh[nj * 2 + 1][1] = th[3];
                bl[nj * 2][0] = tl[0]; bl[nj * 2][1] = tl[1];
                bl[nj * 2 + 1][0] = tl[2]; bl[nj * 2 + 1][1] = tl[3];
            }
#pragma unroll
            for (int mi = 0; mi < 4; mi++)
#pragma unroll
                for (int ni = 0; ni < 4; ni++) {
                    mma16816(acc[mi][ni], ah[mi], bh[ni]);
                    mma16816(acc[mi][ni], ah[mi], bl[ni]);
                    mma16816(acc[mi][ni], al[mi], bh[ni]);
                }
        }
        __syncthreads();   // all warps done with buffer before it's reloaded
    }

    // Epilogue: m16n8 C-frag: row = lane>>2 (+8), col = 2*(lane&3)
#pragma unroll
    for (int mi = 0; mi < 4; mi++) {
#pragma unroll
        for (int ni = 0; ni < 4; ni++) {
            const int row = m0 + wm * 64 + mi * 16 + (lane >> 2);
            const int col = n0 + wn * 32 + ni * 8 + (lane & 3) * 2;
            const float2 bv = *(const float2*)&bias[col];
#pragma unroll
            for (int h = 0; h < 2; h++) {
                float v0 = acc[mi][ni][h * 2 + 0] + bv.x;
                float v1 = acc[mi][ni][h * 2 + 1] + bv.y;
                if (z == 0) {
                    v0 = softplus_acc(v0) + DT_MIN_F;
                    v1 = softplus_acc(v1) + DT_MIN_F;
                }
                float2 o; o.x = v0; o.y = v1;
                *(float2*)&g_proj[z][(size_t)(row + h * 8) * DIM + col] = o;
            }
        }
    }
}

// ---------------------------------------------------------------------------
// Selective scan: 512 thr = 32 channels x 16 states, 8-slot cp.async ring,
// 4 timesteps per barrier pair (2048 barriers total).
// ---------------------------------------------------------------------------
__global__ __launch_bounds__(512)
void ssm_scan(const float* __restrict__ u,
              const float* __restrict__ a_raw,
              const float* __restrict__ Bbase,
              const float* __restrict__ Cbase,
              const float* __restrict__ Dvec,
              float* __restrict__ out, long long out_elems)
{
    __shared__ float s_in[8][4][32];
    __shared__ float s_y[8][32];

    const int tid = threadIdx.x;
    const int b   = blockIdx.y;
    const int d0  = blockIdx.x * 32;
    const int c   = tid >> 4;
    const int n   = tid & 15;
    const int d   = d0 + c;

    const float A  = -softplus_acc(a_raw[d * NST + n]);
    const float Bb = Bbase[d * NST + n];
    const float Cb = Cbase[d * NST + n];
    const float Dd = Dvec[d];

    const size_t ytot = (size_t)BATCH * LSEQ * DIM;
    const size_t ctot = (size_t)BATCH * DIM * NST;
    float* cout = nullptr;
    float* yout = out;
    if ((size_t)out_elems >= ytot + ctot) { cout = out; yout = out + ctot; }

    const int  w      = tid >> 5;
    const int  which  = w & 3;
    const int  toff   = w >> 2;
    const int  lane32 = tid & 31;
    const float* src = (which == 0) ? u : g_proj[which - 1];
    const size_t gbase = ((size_t)b * LSEQ) * DIM + d0 + lane32;

    {
        int tl = toff;
        unsigned daddr = (unsigned)__cvta_generic_to_shared(
            &s_in[tl & 7][which][lane32]);
        const float* gp = src + gbase + (size_t)tl * DIM;
        asm volatile("cp.async.ca.shared.global [%0], [%1], 4;"
                     :: "r"(daddr), "l"(gp));
        asm volatile("cp.async.commit_group;");
    }

    float x = 0.0f;
    const int NGROUPS = LSEQ / 4;
    for (int g = 0; g < NGROUPS; g++) {
        const int t0 = g * 4;
        {
            int tl = t0 + 4 + toff;
            if (tl < LSEQ) {
                unsigned daddr = (unsigned)__cvta_generic_to_shared(
                    &s_in[tl & 7][which][lane32]);
                const float* gp = src + gbase + (size_t)tl * DIM;
                asm volatile("cp.async.ca.shared.global [%0], [%1], 4;"
                             :: "r"(daddr), "l"(gp));
            }
            asm volatile("cp.async.commit_group;");
            asm volatile("cp.async.wait_group 1;");
        }
        __syncthreads();

#pragma unroll
        for (int j = 0; j < 4; j++) {
            const int t   = t0 + j;
            const int cur = t & 7;
            const float uv  = s_in[cur][0][c];
            const float dtv = s_in[cur][1][c];
            const float bv  = s_in[cur][2][c];
            const float cv  = s_in[cur][3][c];

            const float ab = __expf(dtv * A);
            x = fmaf(ab, x, dtv * bv * Bb * uv);
            float contrib = cv * Cb * x;
            contrib += __shfl_xor_sync(0xffffffffu, contrib, 8);
            contrib += __shfl_xor_sync(0xffffffffu, contrib, 4);
            contrib += __shfl_xor_sync(0xffffffffu, contrib, 2);
            contrib += __shfl_xor_sync(0xffffffffu, contrib, 1);
            if (n == 0) s_y[t & 7][c] = contrib + Dd * uv;
        }

        __syncthreads();

        if ((g & 1) && tid < 256) {
            const int r   = tid >> 5;
            const int col = tid & 31;
            const int fb  = 4 * g - 4;
            yout[((size_t)b * LSEQ + (size_t)(fb + r)) * DIM + d0 + col] =
                s_y[r][col];
        }
    }

    if (cout)
        cout[((size_t)b * DIM + d) * NST + n] = x;
}

// ---------------------------------------------------------------------------
// Inputs (metadata order):
// 0:u 1:Wdt 2:bdt 3:Wb 4:bb 5:Wc 6:bc 7:a_raw 8:B_base 9:C_base 10:D
// Output: concat(carry_out[B,d,N], y[B,L,d]) fp32.
// ---------------------------------------------------------------------------
extern "C" void kernel_launch(void* const* d_in, const int* in_sizes, int n_in,
                              void* d_out, int out_size) {
    const float* u     = (const float*)d_in[0];
    const float* Wdt   = (const float*)d_in[1];
    const float* bdt   = (const float*)d_in[2];
    const float* Wb    = (const float*)d_in[3];
    const float* bb    = (const float*)d_in[4];
    const float* Wc    = (const float*)d_in[5];
    const float* bc    = (const float*)d_in[6];
    const float* a_raw = (const float*)d_in[7];
    const float* Bbase = (const float*)d_in[8];
    const float* Cbase = (const float*)d_in[9];
    const float* Dvec  = (const float*)d_in[10];

    // Non-stream call, capture-safe, no static guard.
    cudaFuncSetAttribute(proj_gemm_mma,
                         cudaFuncAttributeMaxDynamicSharedMemorySize,
                         GEMM_SMEM_BYTES);

    // 1) split U into bf16 hi/lo
    conv_u_k<<<(int)(((size_t)M_TOT * DIM) / 1024), 256>>>(u);

    // 2) split+transpose the three weight matrices
    dim3 wgrid(DIM / 32, DIM / 32, 3);
    conv_w_k<<<wgrid, dim3(32, 8)>>>(Wdt, Wb, Wc);

    // 3) HMMA projections (dt gets softplus+DT_MIN in epilogue)
    dim3 ggrid(DIM / 128, M_TOT / 128, 3);
    proj_gemm_mma<<<ggrid, 256, GEMM_SMEM_BYTES>>>(bdt, bb, bc);

    // 4) sequential selective scan
    dim3 sgrid(DIM / 32, BATCH);
    ssm_scan<<<sgrid, 512>>>(u, a_raw, Bbase, Cbase, Dvec,
                             (float*)d_out, (long long)out_size);
}

// round 15
// speedup vs baseline: 1.0343x; 1.0343x over previous
#include <cuda_runtime.h>
#include <cuda_bf16.h>
#include <math.h>
#include <stdint.h>

// Problem constants (SelectiveSSM): B=4, L=4096, d_inner=2048, N=16
#define BATCH 4
#define LSEQ  4096
#define DIM   2048
#define NST   16
#define M_TOT (BATCH * LSEQ)   // 16384
#define DT_MIN_F 1e-4f

#define TK      32             // K elems (bf16) per chunk
#define NCHUNK  (DIM / TK)     // 64

// Padded smem row: 32 data + 8 pad bf16 -> 80B row stride. 8 rows at 80B
// stride land on distinct 16B sub-banks mod 128B -> ldmatrix conflict-free.
#define ROW_E   40
#define TILE_B  (128 * ROW_E * 2)      // bytes (10240)
#define BUF_B   (4 * TILE_B)           // Ah, Al, Bh, Bl (40960)
#define GEMM_SMEM_BYTES (2 * BUF_B)    // double buffer  (81920) -> 2 CTAs/SM

// ---------------- device scratch (static: no dynamic allocation allowed) ----
__device__ float          g_proj[3][(size_t)M_TOT * DIM];       // dt/b/c fp32
__device__ unsigned short g_uhi[(size_t)M_TOT * DIM];           // bf16 hi(U)
__device__ unsigned short g_ulo[(size_t)M_TOT * DIM];           // bf16 lo(U)
__device__ unsigned short g_wthi[3][(size_t)DIM * DIM];         // bf16 hi(W^T)
__device__ unsigned short g_wtlo[3][(size_t)DIM * DIM];         // bf16 lo(W^T)

// ---------------- small helpers --------------------------------------------
__device__ __forceinline__ float softplus_acc(float x) {
    return log1pf(expf(-fabsf(x))) + fmaxf(x, 0.0f);
}
__device__ __forceinline__ unsigned short f2bf(float x) {
    __nv_bfloat16 h = __float2bfloat16(x);
    return *reinterpret_cast<unsigned short*>(&h);
}
__device__ __forceinline__ float bf2f(unsigned short s) {
    __nv_bfloat16 h;
    *reinterpret_cast<unsigned short*>(&h) = s;
    return __bfloat162float(h);
}
__device__ __forceinline__ uint32_t smem_u32(const void* p) {
    uint32_t a;
    asm("{ .reg .u64 t; cvta.to.shared.u64 t, %1; cvt.u32.u64 %0, t; }"
        : "=r"(a) : "l"(p));
    return a;
}
__device__ __forceinline__ void ldsm_x4(uint32_t (&r)[4], uint32_t addr) {
    asm volatile("ldmatrix.sync.aligned.m8n8.x4.shared.b16 {%0,%1,%2,%3}, [%4];"
                 : "=r"(r[0]), "=r"(r[1]), "=r"(r[2]), "=r"(r[3]) : "r"(addr));
}
// D += A(16x16 bf16, row) @ B(16x8 bf16, col), fp32 accum
__device__ __forceinline__ void mma16816(float* c, const uint32_t* a,
                                         const uint32_t* b) {
    asm volatile(
        "mma.sync.aligned.m16n8k16.row.col.f32.bf16.bf16.f32 "
        "{%0,%1,%2,%3}, {%4,%5,%6,%7}, {%8,%9}, {%0,%1,%2,%3};"
        : "+f"(c[0]), "+f"(c[1]), "+f"(c[2]), "+f"(c[3])
        : "r"(a[0]), "r"(a[1]), "r"(a[2]), "r"(a[3]), "r"(b[0]), "r"(b[1]));
}

// ---------------------------------------------------------------------------
// Conversion: U fp32 -> (hi, lo) bf16
// ---------------------------------------------------------------------------
__global__ __launch_bounds__(256)
void conv_u_k(const float* __restrict__ u) {
    size_t i = ((size_t)blockIdx.x * 256 + threadIdx.x) * 4;
    float4 v = *(const float4*)(u + i);
    ushort4 hi, lo;
    hi.x = f2bf(v.x); lo.x = f2bf(v.x - bf2f(hi.x));
    hi.y = f2bf(v.y); lo.y = f2bf(v.y - bf2f(hi.y));
    hi.z = f2bf(v.z); lo.z = f2bf(v.z - bf2f(hi.z));
    hi.w = f2bf(v.w); lo.w = f2bf(v.w - bf2f(hi.w));
    *(ushort4*)(g_uhi + i) = hi;
    *(ushort4*)(g_ulo + i) = lo;
}

// ---------------------------------------------------------------------------
// Conversion + transpose: W[k][n] fp32 -> Wt hi/lo bf16 [n][k]
// ---------------------------------------------------------------------------
__global__ __launch_bounds__(256)
void conv_w_k(const float* __restrict__ Wdt, const float* __restrict__ Wb,
              const float* __restrict__ Wc) {
    const int z = blockIdx.z;
    const float* W = (z == 0) ? Wdt : (z == 1) ? Wb : Wc;
    __shared__ float tile[32][33];
    const int tx = threadIdx.x, ty = threadIdx.y;  // 32 x 8
    const int k0 = blockIdx.y * 32, n0 = blockIdx.x * 32;
#pragma unroll
    for (int i = 0; i < 4; i++)
        tile[ty + 8 * i][tx] = W[(size_t)(k0 + ty + 8 * i) * DIM + n0 + tx];
    __syncthreads();
#pragma unroll
    for (int i = 0; i < 4; i++) {
        const int n = n0 + ty + 8 * i;
        float x = tile[tx][ty + 8 * i];
        unsigned short h = f2bf(x);
        g_wthi[z][(size_t)n * DIM + k0 + tx] = h;
        g_wtlo[z][(size_t)n * DIM + k0 + tx] = f2bf(x - bf2f(h));
    }
}

// ---------------------------------------------------------------------------
// Projection GEMM via mma.sync (HMMA): g_proj[z][m][n] = sum_k U W_z + bias.
// Split-bf16, 3 terms (hi*hi + hi*lo + lo*hi), fp32 accumulators.
// CTA 128x128 tile, 8 warps (2x4), warp tile 64x32 via m16n8k16.
// TK=32 double-buffered cp.async pipeline; 80KB smem -> 2 CTAs/SM.
// z/mb per launch (6 launches/call; lands ncu -s 5 on a GEMM launch).
// ---------------------------------------------------------------------------
__global__ __launch_bounds__(256, 2)
void proj_gemm_mma(int z, int mb,
                   const float* __restrict__ bdt, const float* __restrict__ bb,
                   const float* __restrict__ bc) {
    extern __shared__ __align__(16) unsigned short smem[];
    const uint32_t ubase = smem_u32(smem);

    const int tid  = threadIdx.x;
    const int wid  = tid >> 5, lane = tid & 31;
    const int wm   = wid >> 2;           // warp m 0..1  (64 rows)
    const int wn   = wid & 3;            // warp n 0..3  (32 cols)
    const int m0   = (mb + blockIdx.y) * 128;
    const int n0   = blockIdx.x * 128;

    const unsigned short* Ah = g_uhi;
    const unsigned short* Al = g_ulo;
    const unsigned short* Bh = g_wthi[z];
    const unsigned short* Bl = g_wtlo[z];
    const float* bias = (z == 0) ? bdt : (z == 1) ? bb : bc;

    float acc[4][4][4];
#pragma unroll
    for (int mi = 0; mi < 4; mi++)
#pragma unroll
        for (int ni = 0; ni < 4; ni++)
#pragma unroll
            for (int q = 0; q < 4; q++) acc[mi][ni][q] = 0.0f;

    // Staging: 512 16B-chunks per tile / 256 thr = 2 per thread per tile.
    const int srow = tid >> 2;     // 0..63 (+64 per i)
    const int sc4  = tid & 3;      // 16B unit within the 64B data of a row
    auto load_chunk = [&](int c) {
        const uint32_t bufb = ubase + (uint32_t)(c & 1) * BUF_B;
        const int k0 = c * TK;
        const unsigned short* srcs[4] = { Ah, Al, Bh, Bl };
#pragma unroll
        for (int t = 0; t < 4; t++) {
            const int row0 = (t < 2) ? m0 : n0;
            const unsigned short* sp = srcs[t];
            const uint32_t tb = bufb + (uint32_t)t * TILE_B;
#pragma unroll
            for (int i = 0; i < 2; i++) {
                const int row = srow + i * 64;
                const unsigned short* gp =
                    sp + (size_t)(row0 + row) * DIM + k0 + sc4 * 8;
                const uint32_t so = tb + (uint32_t)(row * ROW_E + sc4 * 8) * 2;
                asm volatile("cp.async.cg.shared.global [%0], [%1], 16;"
                             :: "r"(so), "l"(gp));
            }
        }
        asm volatile("cp.async.commit_group;" ::: "memory");
    };

    load_chunk(0);   // prime

    // Per-lane fragment geometry
    const int ar   = wm * 64 + (lane & 15);   // A row
    const int ak   = (lane >> 4) * 8;         // A k-half within k16
    const int bsub = lane >> 3;               // 0..3
    const int brw  = lane & 7;
    const int bkg  = (bsub & 1) * 8;          // B k-half
    const int bnt  = bsub >> 1;               // B n-tile within pair

    for (int c = 0; c < NCHUNK; c++) {
        const uint32_t bufb = ubase + (uint32_t)(c & 1) * BUF_B;
        if (c + 1 < NCHUNK) {
            load_chunk(c + 1);
            asm volatile("cp.async.wait_group 1;" ::: "memory");
        } else {
            asm volatile("cp.async.wait_group 0;" ::: "memory");
        }
        __syncthreads();   // chunk c resident for all warps

        const uint32_t Ahb = bufb;
        const uint32_t Alb = bufb + TILE_B;
        const uint32_t Bhb = bufb + 2 * TILE_B;
        const uint32_t Blb = bufb + 3 * TILE_B;

#pragma unroll
        for (int ks = 0; ks < 2; ks++) {
            // B frags for this k16 (shared across all mi)
            uint32_t bh[4][2], bl[4][2];
#pragma unroll
            for (int nj = 0; nj < 2; nj++) {
                const int brow = wn * 32 + (nj * 2 + bnt) * 8 + brw;
                const uint32_t off =
                    (uint32_t)(brow * ROW_E + ks * 16 + bkg) * 2;
                uint32_t th[4], tl[4];
                ldsm_x4(th, Bhb + off);
                ldsm_x4(tl, Blb + off);
                bh[nj * 2][0] = th[0]; bh[nj * 2][1] = th[1];
                bh[nj * 2 + 1][0] = th[2]; bh[nj * 2 + 1][1] = th[3];
                bl[nj * 2][0] = tl[0]; bl[nj * 2][1] = tl[1];
                bl[nj * 2 + 1][0] = tl[2]; bl[nj * 2 + 1][1] = tl[3];
            }
            // A frags in 2 mi-halves to bound live registers
#pragma unroll
            for (int half = 0; half < 2; half++) {
                uint32_t ah[2][4], al[2][4];
#pragma unroll
                for (int m2 = 0; m2 < 2; m2++) {
                    const int mi = half * 2 + m2;
                    const uint32_t off =
                        (uint32_t)((ar + mi * 16) * ROW_E + ks * 16 + ak) * 2;
                    ldsm_x4(ah[m2], Ahb + off);
                    ldsm_x4(al[m2], Alb + off);
                }
#pragma unroll
                for (int m2 = 0; m2 < 2; m2++) {
                    const int mi = half * 2 + m2;
#pragma unroll
                    for (int ni = 0; ni < 4; ni++) {
                        mma16816(acc[mi][ni], ah[m2], bh[ni]);
                        mma16816(acc[mi][ni], ah[m2], bl[ni]);
                        mma16816(acc[mi][ni], al[m2], bh[ni]);
                    }
                }
            }
        }
        __syncthreads();   // all warps done with buffer before it's reloaded
    }

    // Epilogue: m16n8 C-frag: row = lane>>2 (+8), col = 2*(lane&3)
#pragma unroll
    for (int mi = 0; mi < 4; mi++) {
#pragma unroll
        for (int ni = 0; ni < 4; ni++) {
            const int row = m0 + wm * 64 + mi * 16 + (lane >> 2);
            const int col = n0 + wn * 32 + ni * 8 + (lane & 3) * 2;
            const float2 bv = *(const float2*)&bias[col];
#pragma unroll
            for (int h = 0; h < 2; h++) {
                float v0 = acc[mi][ni][h * 2 + 0] + bv.x;
                float v1 = acc[mi][ni][h * 2 + 1] + bv.y;
                if (z == 0) {
                    v0 = softplus_acc(v0) + DT_MIN_F;
                    v1 = softplus_acc(v1) + DT_MIN_F;
                }
                float2 o; o.x = v0; o.y = v1;
                *(float2*)&g_proj[z][(size_t)(row + h * 8) * DIM + col] = o;
            }
        }
    }
}

// ---------------------------------------------------------------------------
// Selective scan: 512 thr = 32 channels x 16 states, 16-slot cp.async ring,
// 8 timesteps per barrier pair (1024 barriers total).
// Warp w stages array (w&3) at timestep offsets {w>>2, (w>>2)+4}.
// ---------------------------------------------------------------------------
__global__ __launch_bounds__(512)
void ssm_scan(const float* __restrict__ u,
              const float* __restrict__ a_raw,
              const float* __restrict__ Bbase,
              const float* __restrict__ Cbase,
              const float* __restrict__ Dvec,
              float* __restrict__ out, long long out_elems)
{
    __shared__ float s_in[16][4][32];  // [ring slot][{u,dt,b,c}][channel]
    __shared__ float s_y[8][32];

    const int tid = threadIdx.x;
    const int b   = blockIdx.y;
    const int d0  = blockIdx.x * 32;
    const int c   = tid >> 4;
    const int n   = tid & 15;
    const int d   = d0 + c;

    const float A  = -softplus_acc(a_raw[d * NST + n]);
    const float Bb = Bbase[d * NST + n];
    const float Cb = Cbase[d * NST + n];
    const float Dd = Dvec[d];

    const size_t ytot = (size_t)BATCH * LSEQ * DIM;
    const size_t ctot = (size_t)BATCH * DIM * NST;
    float* cout = nullptr;
    float* yout = out;
    if ((size_t)out_elems >= ytot + ctot) { cout = out; yout = out + ctot; }

    const int  w      = tid >> 5;
    const int  which  = w & 3;
    const int  toff   = w >> 2;       // 0..3
    const int  lane32 = tid & 31;
    const float* src = (which == 0) ? u : g_proj[which - 1];
    const size_t gbase = ((size_t)b * LSEQ) * DIM + d0 + lane32;

    // Prime: group 0 (t = 0..7)
#pragma unroll
    for (int q = 0; q < 2; q++) {
        const int tl = toff + q * 4;
        unsigned daddr = (unsigned)__cvta_generic_to_shared(
            &s_in[tl & 15][which][lane32]);
        const float* gp = src + gbase + (size_t)tl * DIM;
        asm volatile("cp.async.ca.shared.global [%0], [%1], 4;"
                     :: "r"(daddr), "l"(gp));
    }
    asm volatile("cp.async.commit_group;");

    float x = 0.0f;
    const int NGROUPS = LSEQ / 8;    // 512
    for (int g = 0; g < NGROUPS; g++) {
        const int t0 = g * 8;

        // Prefetch group g+1 (t0+8 .. t0+15)
#pragma unroll
        for (int q = 0; q < 2; q++) {
            const int tl = t0 + 8 + toff + q * 4;
            if (tl < LSEQ) {
                unsigned daddr = (unsigned)__cvta_generic_to_shared(
                    &s_in[tl & 15][which][lane32]);
                const float* gp = src + gbase + (size_t)tl * DIM;
                asm volatile("cp.async.ca.shared.global [%0], [%1], 4;"
                             :: "r"(daddr), "l"(gp));
            }
        }
        asm volatile("cp.async.commit_group;");
        asm volatile("cp.async.wait_group 1;");   // group g complete
        __syncthreads();

#pragma unroll
        for (int j = 0; j < 8; j++) {
            const int t   = t0 + j;
            const int cur = t & 15;
            const float uv  = s_in[cur][0][c];
            const float dtv = s_in[cur][1][c];
            const float bv  = s_in[cur][2][c];
            const float cv  = s_in[cur][3][c];

            const float ab = __expf(dtv * A);
            x = fmaf(ab, x, dtv * bv * Bb * uv);
            float contrib = cv * Cb * x;
            contrib += __shfl_xor_sync(0xffffffffu, contrib, 8);
            contrib += __shfl_xor_sync(0xffffffffu, contrib, 4);
            contrib += __shfl_xor_sync(0xffffffffu, contrib, 2);
            contrib += __shfl_xor_sync(0xffffffffu, contrib, 1);
            if (n == 0) s_y[j][c] = contrib + Dd * uv;
        }

        __syncthreads();   // s_y complete; all reads of group g done

        if (tid < 256) {   // flush 8 rows: t0 .. t0+7
            const int r   = tid >> 5;
            const int col = tid & 31;
            yout[((size_t)b * LSEQ + (size_t)(t0 + r)) * DIM + d0 + col] =
                s_y[r][col];
        }
    }

    if (cout)
        cout[((size_t)b * DIM + d) * NST + n] = x;
}

// ---------------------------------------------------------------------------
// Inputs (metadata order):
// 0:u 1:Wdt 2:bdt 3:Wb 4:bb 5:Wc 6:bc 7:a_raw 8:B_base 9:C_base 10:D
// Output: concat(carry_out[B,d,N], y[B,L,d]) fp32.
// ---------------------------------------------------------------------------
extern "C" void kernel_launch(void* const* d_in, const int* in_sizes, int n_in,
                              void* d_out, int out_size) {
    const float* u     = (const float*)d_in[0];
    const float* Wdt   = (const float*)d_in[1];
    const float* bdt   = (const float*)d_in[2];
    const float* Wb    = (const float*)d_in[3];
    const float* bb    = (const float*)d_in[4];
    const float* Wc    = (const float*)d_in[5];
    const float* bc    = (const float*)d_in[6];
    const float* a_raw = (const float*)d_in[7];
    const float* Bbase = (const float*)d_in[8];
    const float* Cbase = (const float*)d_in[9];
    const float* Dvec  = (const float*)d_in[10];

    // Non-stream call, capture-safe, no static guard.
    cudaFuncSetAttribute(proj_gemm_mma,
                         cudaFuncAttributeMaxDynamicSharedMemorySize,
                         GEMM_SMEM_BYTES);

    // 1) split U into bf16 hi/lo
    conv_u_k<<<(int)(((size_t)M_TOT * DIM) / 1024), 256>>>(u);

    // 2) split+transpose the three weight matrices
    dim3 wgrid(DIM / 32, DIM / 32, 3);
    conv_w_k<<<wgrid, dim3(32, 8)>>>(Wdt, Wb, Wc);

    // 3) HMMA projections, 6 launches (z x m-half)
    dim3 ggrid(DIM / 128, M_TOT / 128 / 2);   // (16, 64)
    for (int z = 0; z < 3; z++)
        for (int mh = 0; mh < 2; mh++)
            proj_gemm_mma<<<ggrid, 256, GEMM_SMEM_BYTES>>>(
                z, mh * 64, bdt, bb, bc);

    // 4) sequential selective scan
    dim3 sgrid(DIM / 32, BATCH);
    ssm_scan<<<sgrid, 512>>>(u, a_raw, Bbase, Cbase, Dvec,
                             (float*)d_out, (long long)out_size);
}